// round 14
// baseline (speedup 1.0000x reference)
#include <cuda_runtime.h>
#include <cuda_fp16.h>
#include <cstdint>

// Problem constants
#define E_    131072
#define G_    64
#define ED_   2049
#define KIN_  2055
#define EMB_  625
#define HID_  128
#define OUT_  2
#define EPSF  1e-5f

#define KP1   2112     // padded K for layer 1 (multiple of 64)
#define HP    640      // padded N / K pitch for h buffers & weights
#define STAGES 3
#define STAGE_BYTES 32768   // A 16KB + B 16KB (128 rows x 128B, k-tile = 64 halves)
#define NBLK  512           // E_/256 edge-processing blocks

// ---------------- device scratch (allocation-free) ----------------
__device__ __half g_A1[(size_t)E_ * KP1];    // sorted edge order
__device__ __half g_h1[(size_t)E_ * HP];
__device__ __half g_h2[(size_t)E_ * HP];
__device__ __half g_W1t[HP * KP1];
__device__ __half g_W2t[HP * HP];
__device__ __half g_W3t[HP * HP];
__device__ __half g_Wf1t[HID_ * HP];
__device__ float g_s1[EMB_], g_t1[EMB_];
__device__ float g_s2[EMB_], g_t2[EMB_];
__device__ float g_c0[HID_];
__device__ int   g_ebatch[E_];       // batch id per edge (original order)
__device__ int   g_perm[E_];         // sorted-pos -> original edge
__device__ int   g_ebatch_s[E_];     // batch id per sorted pos
__device__ int   g_bhist[NBLK * G_]; // per-block hist -> per-block base
__device__ float g_cnt[G_];
__device__ float g_gsum[G_ * HID_];

// ---------------- helpers ----------------
__device__ __forceinline__ uint32_t smem_u32(const void* p) {
    return (uint32_t)__cvta_generic_to_shared(p);
}
__device__ __forceinline__ void cp16(uint32_t dst, const void* src) {
    asm volatile("cp.async.cg.shared.global [%0], [%1], 16;\n" :: "r"(dst), "l"(src));
}
#define CP_COMMIT() asm volatile("cp.async.commit_group;\n" ::: "memory")
#define CP_WAIT1()  asm volatile("cp.async.wait_group 1;\n" ::: "memory")
#define CP_WAIT0()  asm volatile("cp.async.wait_group 0;\n" ::: "memory")

__device__ __forceinline__ void ldsm4(uint32_t& r0, uint32_t& r1, uint32_t& r2, uint32_t& r3,
                                      uint32_t addr) {
    asm volatile("ldmatrix.sync.aligned.m8n8.x4.shared.b16 {%0,%1,%2,%3}, [%4];"
                 : "=r"(r0), "=r"(r1), "=r"(r2), "=r"(r3) : "r"(addr));
}

#define MMA_F16(d, a, b0, b1)                                           \
    asm volatile(                                                       \
        "mma.sync.aligned.m16n8k16.row.col.f32.f16.f16.f32 "            \
        "{%0,%1,%2,%3}, {%4,%5,%6,%7}, {%8,%9}, {%0,%1,%2,%3};"         \
        : "+f"(d[0]), "+f"(d[1]), "+f"(d[2]), "+f"(d[3])                \
        : "r"(a[0]), "r"(a[1]), "r"(a[2]), "r"(a[3]), "r"(b0), "r"(b1))

// ---------------- small prep kernels (edge sort chain) ----------------
// per-block histogram of batch ids (no global atomics)
__global__ void prep_edge_kernel(const int* __restrict__ eidx,
                                 const int* __restrict__ batch)
{
    __shared__ int hist[G_];
    int t = threadIdx.x;
    if (t < G_) hist[t] = 0;
    __syncthreads();
    int e = blockIdx.x * blockDim.x + t;
    int b = batch[eidx[e]];
    g_ebatch[e] = b;
    atomicAdd(&hist[b], 1);
    __syncthreads();
    if (t < G_) g_bhist[blockIdx.x * G_ + t] = hist[t];
}

// column prefix: g_bhist[blk][b] -> global base for (blk, b); g_cnt[b] = total
__global__ void prep_prefix_kernel()   // 1 block, 64 threads
{
    __shared__ int tot[G_];
    int b = threadIdx.x;
    int t = 0;
    for (int blk = 0; blk < NBLK; blk++) t += g_bhist[blk * G_ + b];
    tot[b] = t;
    g_cnt[b] = (float)t;
    __syncthreads();
    int off = 0;
    for (int i = 0; i < b; i++) off += tot[i];
    int run = off;
    for (int blk = 0; blk < NBLK; blk++) {
        int h = g_bhist[blk * G_ + b];
        g_bhist[blk * G_ + b] = run;
        run += h;
    }
}

__global__ void scatter_kernel()
{
    __shared__ int cnt[G_];
    int t = threadIdx.x;
    if (t < G_) cnt[t] = 0;
    __syncthreads();
    int e = blockIdx.x * blockDim.x + t;
    int b = g_ebatch[e];
    int r = atomicAdd(&cnt[b], 1);
    int pos = g_bhist[blockIdx.x * G_ + b] + r;
    g_perm[pos] = e;
    g_ebatch_s[pos] = b;
}

// ---------------- mega prep: A1 build + weight transposes + c0/affines ----------------
#define WSEG1 ((size_t)HP * KP1)
#define WSEG2 (WSEG1 + (size_t)HP * HP)
#define WSEG3 (WSEG2 + (size_t)HP * HP)
#define WSEG4 (WSEG3 + (size_t)HID_ * HP)
#define NWBLK ((int)((WSEG4 + 255) / 256))

__global__ void megaprep_kernel(const float* __restrict__ ea,
                                const float* __restrict__ arr,
                                const int* __restrict__ eidx,
                                const float* __restrict__ W1, const float* __restrict__ W2,
                                const float* __restrict__ W3, const float* __restrict__ Wf1,
                                const float* __restrict__ g1, const float* __restrict__ be1,
                                const float* __restrict__ m1, const float* __restrict__ v1,
                                const float* __restrict__ g2, const float* __restrict__ be2,
                                const float* __restrict__ m2, const float* __restrict__ v2,
                                const float* __restrict__ g3, const float* __restrict__ be3,
                                const float* __restrict__ m3, const float* __restrict__ v3)
{
    const int p = blockIdx.x;
    const int t = threadIdx.x;

    if (p < E_) {
        // ---- build fp16 concatenated A1 row p <- edge perm[p] ----
        const int e = g_perm[p];
        const float* src = ea + (size_t)e * ED_;
        __half* dst = g_A1 + (size_t)p * KP1;
        for (int q = t; q < 512; q += blockDim.x) {
            int k = q * 4;
            float f0 = src[k], f1 = src[k + 1], f2 = src[k + 2], f3 = src[k + 3];
            __half2 p0 = __floats2half2_rn(f0, f1);
            __half2 p1 = __floats2half2_rn(f2, f3);
            uint2 u;
            u.x = *(uint32_t*)&p0;
            u.y = *(uint32_t*)&p1;
            *(uint2*)(dst + k) = u;
        }
        if (t < 64) {
            int k = 2048 + t;
            float v;
            if (k < ED_) {
                v = src[k];
            } else if (k < ED_ + 3) {
                v = arr[3 * eidx[e] + (k - ED_)];
            } else if (k < ED_ + 6) {
                v = arr[3 * eidx[E_ + e] + (k - ED_ - 3)];
            } else {
                v = 0.0f;
            }
            dst[k] = __float2half_rn(v);
        }
    } else if (p < E_ + NWBLK) {
        // ---- transposed weights (flat index) ----
        size_t idx = (size_t)(p - E_) * 256 + t;
        if (idx < WSEG1) {
            int n = (int)(idx / KP1), k = (int)(idx % KP1);
            float v = (k < KIN_ && n < EMB_) ? W1[(size_t)k * EMB_ + n] : 0.0f;
            g_W1t[idx] = __float2half_rn(v);
        } else if (idx < WSEG2) {
            size_t j = idx - WSEG1;
            int n = (int)(j / HP), k = (int)(j % HP);
            float v = (k < EMB_ && n < EMB_) ? W2[(size_t)k * EMB_ + n] : 0.0f;
            g_W2t[j] = __float2half_rn(v);
        } else if (idx < WSEG3) {
            size_t j = idx - WSEG2;
            int n = (int)(j / HP), k = (int)(j % HP);
            float v = (k < EMB_ && n < EMB_) ? W3[(size_t)k * EMB_ + n] : 0.0f;
            g_W3t[j] = __float2half_rn(v);
        } else if (idx < WSEG4) {
            size_t j = idx - WSEG3;
            int n = (int)(j / HP), k = (int)(j % HP);
            float v = 0.0f;
            if (k < EMB_ && n < HID_) {
                float s3 = g3[k] / sqrtf(v3[k] + EPSF);   // identical formula to r12
                v = Wf1[(size_t)k * HID_ + n] * s3;
            }
            g_Wf1t[j] = __float2half_rn(v);
        }
    } else {
        // ---- tail block: c0, BN affines for layers 1/2, zero gsum ----
        if (t < HID_) {
            float c0 = 0.0f;
            for (int k = 0; k < EMB_; k++) {
                float s3 = g3[k] / sqrtf(v3[k] + EPSF);
                float t3 = be3[k] - m3[k] * s3;
                c0 = fmaf(t3, Wf1[k * HID_ + t], c0);
            }
            g_c0[t] = c0;
        }
        for (int i = t; i < EMB_; i += 256) {
            float s1 = g1[i] / sqrtf(v1[i] + EPSF);
            g_s1[i] = s1; g_t1[i] = be1[i] - m1[i] * s1;
            float s2 = g2[i] / sqrtf(v2[i] + EPSF);
            g_s2[i] = s2; g_t2[i] = be2[i] - m2[i] * s2;
        }
        for (int i = t; i < G_ * HID_; i += 256) g_gsum[i] = 0.0f;
    }
}

// ---------------- fp16 tensor-core GEMM: cp.async pipeline + ldmatrix ----------------
//   emode 0: h = max(z + bias, 0) * scale + shift  -> fp16 store (0 for n >= Nreal)
//   emode 3: p = max(z + bias, 0) -> smem; fused pool: p @ Wf1t[k=col0..col0+128)
//            -> segment-sum into g_gsum (rows are batch-sorted). No global store.
__global__ __launch_bounds__(128)
void gemm_f16(const __half* __restrict__ A, int lda,
              const __half* __restrict__ Bt, int ldbt,
              const float* __restrict__ bias,
              const float* __restrict__ scale,
              const float* __restrict__ shift,
              __half* __restrict__ C, int ldc,
              int Nreal, int ktiles, int emode)
{
    extern __shared__ __align__(16) char smem_raw[];
    const uint32_t sb = smem_u32(smem_raw);

    const int tid  = threadIdx.x;
    const int lane = tid & 31;
    const int w    = tid >> 5;            // 0..3
    const int wm   = (w & 1) * 64;
    const int wn   = (w >> 1) * 64;
    const int row0 = blockIdx.y * 128;
    const int col0 = blockIdx.x * 128;

    const __half* Abase = A  + (size_t)row0 * lda;
    const __half* Bbase = Bt + (size_t)col0 * ldbt;

    // ldmatrix lane address components
    const int rA  = wm + (lane & 15);
    const int hiA = lane >> 4;
    const int xa  = rA & 7;
    const int rB  = wn + ((lane >> 4) & 1) * 8 + (lane & 7);
    const int hiB = (lane >> 3) & 1;
    const int xb  = rB & 7;

    float acc[4][8][4];
#pragma unroll
    for (int mi = 0; mi < 4; mi++)
#pragma unroll
        for (int ni = 0; ni < 8; ni++)
#pragma unroll
            for (int c = 0; c < 4; c++) acc[mi][ni][c] = 0.0f;

    auto stage = [&](int s, int kt) {
        uint32_t sA = sb + s * STAGE_BYTES;
        uint32_t sB = sA + 16384;
        const __half* Ak = Abase + kt * 64;
        const __half* Bk = Bbase + kt * 64;
#pragma unroll
        for (int i = 0; i < 8; i++) {
            int id = i * 128 + tid;
            int m  = id >> 3;
            int c  = id & 7;
            cp16(sA + m * 128 + ((c ^ (m & 7)) << 4), Ak + (size_t)m * lda + c * 8);
        }
#pragma unroll
        for (int i = 0; i < 8; i++) {
            int id = i * 128 + tid;
            int n  = id >> 3;
            int c  = id & 7;
            cp16(sB + n * 128 + ((c ^ (n & 7)) << 4), Bk + (size_t)n * ldbt + c * 8);
        }
    };

    // the shared inner-loop body over one staged ktile
    auto compute_tile = [&](uint32_t sA, uint32_t sB) {
#pragma unroll
        for (int k16 = 0; k16 < 4; k16++) {
            uint32_t a[4][4];
#pragma unroll
            for (int mi = 0; mi < 4; mi++) {
                uint32_t addr = sA + (rA + mi * 16) * 128
                              + ((uint32_t)((k16 * 2 + hiA) ^ xa) << 4);
                ldsm4(a[mi][0], a[mi][1], a[mi][2], a[mi][3], addr);
            }
            uint32_t bf[4][4];
#pragma unroll
            for (int nj = 0; nj < 4; nj++) {
                uint32_t addr = sB + (rB + nj * 16) * 128
                              + ((uint32_t)((k16 * 2 + hiB) ^ xb) << 4);
                ldsm4(bf[nj][0], bf[nj][1], bf[nj][2], bf[nj][3], addr);
            }
#pragma unroll
            for (int mi = 0; mi < 4; mi++) {
#pragma unroll
                for (int nj = 0; nj < 4; nj++) {
                    MMA_F16(acc[mi][2 * nj],     a[mi], bf[nj][0], bf[nj][1]);
                    MMA_F16(acc[mi][2 * nj + 1], a[mi], bf[nj][2], bf[nj][3]);
                }
            }
        }
    };

    // prologue: stages 0 and 1
    stage(0, 0);
    CP_COMMIT();
    stage(1, 1);
    CP_COMMIT();

    for (int kt = 0; kt < ktiles; kt++) {
        CP_WAIT1();          // stage kt arrived (allow kt+1 pending)
        __syncthreads();     // all threads past compute(kt-1) -> safe to overwrite

        int pf = kt + 2;
        if (pf < ktiles) stage(pf % STAGES, pf);
        CP_COMMIT();

        const int s = kt % STAGES;
        compute_tile(sb + s * STAGE_BYTES, sb + s * STAGE_BYTES + 16384);
    }

    // ---- epilogue ----
    const int g  = lane >> 2;
    const int tg = lane & 3;

    if (emode == 0) {
#pragma unroll
        for (int mi = 0; mi < 4; mi++) {
            int r_lo = row0 + wm + mi * 16 + g;
            __half* crow_lo = C + (size_t)r_lo * ldc;
            __half* crow_hi = crow_lo + (size_t)8 * ldc;
#pragma unroll
            for (int ni = 0; ni < 8; ni++) {
                int cc = col0 + wn + ni * 8 + tg * 2;
                float z0 = 0.0f, z1 = 0.0f, z2 = 0.0f, z3 = 0.0f;
                if (cc < Nreal) {
                    float b0 = bias[cc];
                    float sc0 = scale[cc], sh0 = shift[cc];
                    z0 = fmaxf(acc[mi][ni][0] + b0, 0.0f) * sc0 + sh0;
                    z2 = fmaxf(acc[mi][ni][2] + b0, 0.0f) * sc0 + sh0;
                }
                if (cc + 1 < Nreal) {
                    float b1 = bias[cc + 1];
                    float sc1 = scale[cc + 1], sh1 = shift[cc + 1];
                    z1 = fmaxf(acc[mi][ni][1] + b1, 0.0f) * sc1 + sh1;
                    z3 = fmaxf(acc[mi][ni][3] + b1, 0.0f) * sc1 + sh1;
                }
                *(__half2*)&crow_lo[cc] = __floats2half2_rn(z0, z1);
                *(__half2*)&crow_hi[cc] = __floats2half2_rn(z2, z3);
            }
        }
        return;
    }

    // ======== emode 3: layer 3 with fused pool ========
    __syncthreads();   // all warps done with stage smem

    // stage Wf1t slices (k = col0 + it*64, n = 0..127) into B-areas of stages 0,1
#pragma unroll
    for (int it = 0; it < 2; it++) {
        uint32_t sB = sb + it * STAGE_BYTES + 16384;
        const __half* Bk = g_Wf1t + col0 + it * 64;
#pragma unroll
        for (int i = 0; i < 8; i++) {
            int id = i * 128 + tid;
            int n  = id >> 3;
            int c  = id & 7;
            cp16(sB + n * 128 + ((c ^ (n & 7)) << 4), Bk + (size_t)n * HP + c * 8);
        }
    }
    CP_COMMIT();

    // store p = fp16(relu(z + b3)) into A-areas of stages 0,1 (same swizzle)
#pragma unroll
    for (int mi = 0; mi < 4; mi++) {
        int m_lo = wm + mi * 16 + g;     // block-local rows
        int m_hi = m_lo + 8;
#pragma unroll
        for (int ni = 0; ni < 8; ni++) {
            int cc = wn + ni * 8 + tg * 2;          // block-local col 0..127
            int gcc = col0 + cc;
            float z0 = 0.0f, z1 = 0.0f, z2 = 0.0f, z3 = 0.0f;
            if (gcc < Nreal) {
                float b0 = bias[gcc];
                z0 = fmaxf(acc[mi][ni][0] + b0, 0.0f);
                z2 = fmaxf(acc[mi][ni][2] + b0, 0.0f);
            }
            if (gcc + 1 < Nreal) {
                float b1 = bias[gcc + 1];
                z1 = fmaxf(acc[mi][ni][1] + b1, 0.0f);
                z3 = fmaxf(acc[mi][ni][3] + b1, 0.0f);
            }
            int it = cc >> 6;                       // which stage A-area
            int jp = (cc & 63) >> 1;                // half2 pair index 0..31
            int chunk = jp >> 2;                    // 16B chunk 0..7
            int within = (jp & 3) * 4;
            __half2 h_lo = __floats2half2_rn(z0, z1);
            __half2 h_hi = __floats2half2_rn(z2, z3);
            char* a_area = smem_raw + it * STAGE_BYTES;
            *(uint32_t*)(a_area + m_lo * 128 + ((chunk ^ (m_lo & 7)) << 4) + within)
                = *(uint32_t*)&h_lo;
            *(uint32_t*)(a_area + m_hi * 128 + ((chunk ^ (m_hi & 7)) << 4) + within)
                = *(uint32_t*)&h_hi;
        }
    }

    CP_WAIT0();
    __syncthreads();

    // pool GEMM: 2 ktile iterations, acc reused as 128x128 pool accumulator
#pragma unroll
    for (int mi = 0; mi < 4; mi++)
#pragma unroll
        for (int ni = 0; ni < 8; ni++)
#pragma unroll
            for (int c = 0; c < 4; c++) acc[mi][ni][c] = 0.0f;

    compute_tile(sb, sb + 16384);
    compute_tile(sb + STAGE_BYTES, sb + STAGE_BYTES + 16384);

    // segment-sum epilogue (rows batch-sorted)
    {
        const int b0 = g_ebatch_s[row0];
        const int bL = g_ebatch_s[row0 + 127];
        if (b0 == bL) {
            float s[8][2];
#pragma unroll
            for (int ni = 0; ni < 8; ni++) {
                s[ni][0] = 0.0f; s[ni][1] = 0.0f;
#pragma unroll
                for (int mi = 0; mi < 4; mi++) {
                    s[ni][0] += acc[mi][ni][0] + acc[mi][ni][2];
                    s[ni][1] += acc[mi][ni][1] + acc[mi][ni][3];
                }
            }
#pragma unroll
            for (int off = 4; off <= 16; off <<= 1) {
#pragma unroll
                for (int ni = 0; ni < 8; ni++) {
                    s[ni][0] += __shfl_xor_sync(0xffffffffu, s[ni][0], off);
                    s[ni][1] += __shfl_xor_sync(0xffffffffu, s[ni][1], off);
                }
            }
            __shared__ float red[2][128];
            if (lane < 4) {
#pragma unroll
                for (int ni = 0; ni < 8; ni++) {
                    red[wm >> 6][wn + ni * 8 + lane * 2 + 0] = s[ni][0];
                    red[wm >> 6][wn + ni * 8 + lane * 2 + 1] = s[ni][1];
                }
            }
            __syncthreads();
            atomicAdd(&g_gsum[b0 * HID_ + tid], red[0][tid] + red[1][tid]);
        } else {
#pragma unroll
            for (int mi = 0; mi < 4; mi++) {
                int r_lo = row0 + wm + mi * 16 + g;
                int b_lo = g_ebatch_s[r_lo];
                int b_hi = g_ebatch_s[r_lo + 8];
#pragma unroll
                for (int ni = 0; ni < 8; ni++) {
                    int cc = wn + ni * 8 + tg * 2;
                    atomicAdd(&g_gsum[b_lo * HID_ + cc],     acc[mi][ni][0]);
                    atomicAdd(&g_gsum[b_lo * HID_ + cc + 1], acc[mi][ni][1]);
                    atomicAdd(&g_gsum[b_hi * HID_ + cc],     acc[mi][ni][2]);
                    atomicAdd(&g_gsum[b_hi * HID_ + cc + 1], acc[mi][ni][3]);
                }
            }
        }
    }
}

// ---------------- head: mean + 2-layer MLP ----------------
__global__ void head_kernel(const float* __restrict__ bf1,
                            const float* __restrict__ Wf2,
                            const float* __restrict__ bf2,
                            float* __restrict__ out)
{
    const int g = blockIdx.x;
    const int n = threadIdx.x;
    float cnt = g_cnt[g];
    float v = (cnt > 0.0f) ? (g_gsum[g * HID_ + n] / cnt + g_c0[n]) : 0.0f;
    float h = fmaxf(v + bf1[n], 0.0f);

    __shared__ float s0[HID_], s1[HID_];
    s0[n] = h * Wf2[n * OUT_ + 0];
    s1[n] = h * Wf2[n * OUT_ + 1];
    __syncthreads();
    for (int off = HID_ / 2; off > 0; off >>= 1) {
        if (n < off) { s0[n] += s0[n + off]; s1[n] += s1[n + off]; }
        __syncthreads();
    }
    if (n == 0) {
        out[g * OUT_ + 0] = s0[0] + bf2[0];
        out[g * OUT_ + 1] = s1[0] + bf2[1];
    }
}

// ---------------- launch ----------------
extern "C" void kernel_launch(void* const* d_in, const int* in_sizes, int n_in,
                              void* d_out, int out_size)
{
    (void)in_sizes; (void)n_in; (void)out_size;

    const float* edge_attr = (const float*)d_in[0];
    const float* arr       = (const float*)d_in[1];
    const int*   eidx      = (const int*)d_in[2];
    const int*   batch     = (const int*)d_in[3];
    const float *W1 = (const float*)d_in[4],  *b1 = (const float*)d_in[5];
    const float *g1 = (const float*)d_in[6],  *be1 = (const float*)d_in[7];
    const float *m1 = (const float*)d_in[8],  *v1 = (const float*)d_in[9];
    const float *W2 = (const float*)d_in[10], *b2 = (const float*)d_in[11];
    const float *g2 = (const float*)d_in[12], *be2 = (const float*)d_in[13];
    const float *m2 = (const float*)d_in[14], *v2 = (const float*)d_in[15];
    const float *W3 = (const float*)d_in[16], *b3 = (const float*)d_in[17];
    const float *g3 = (const float*)d_in[18], *be3 = (const float*)d_in[19];
    const float *m3 = (const float*)d_in[20], *v3 = (const float*)d_in[21];
    const float *Wf1 = (const float*)d_in[22], *bf1 = (const float*)d_in[23];
    const float *Wf2 = (const float*)d_in[24], *bf2 = (const float*)d_in[25];
    float* out = (float*)d_out;

    __half *a1, *h1, *h2, *w1t, *w2t, *w3t;
    float *s1p, *t1p, *s2p, *t2p;
    cudaGetSymbolAddress((void**)&a1,   g_A1);
    cudaGetSymbolAddress((void**)&h1,   g_h1);
    cudaGetSymbolAddress((void**)&h2,   g_h2);
    cudaGetSymbolAddress((void**)&w1t,  g_W1t);
    cudaGetSymbolAddress((void**)&w2t,  g_W2t);
    cudaGetSymbolAddress((void**)&w3t,  g_W3t);
    cudaGetSymbolAddress((void**)&s1p,  g_s1);
    cudaGetSymbolAddress((void**)&t1p,  g_t1);
    cudaGetSymbolAddress((void**)&s2p,  g_s2);
    cudaGetSymbolAddress((void**)&t2p,  g_t2);

    cudaFuncSetAttribute(gemm_f16, cudaFuncAttributeMaxDynamicSharedMemorySize,
                         STAGES * STAGE_BYTES);

    // prep: edge sort chain, then one fused mega-prep (A1 + weights + c0/affines)
    prep_edge_kernel<<<NBLK, 256>>>(eidx, batch);
    prep_prefix_kernel<<<1, G_>>>();
    scatter_kernel<<<NBLK, 256>>>();
    megaprep_kernel<<<E_ + NWBLK + 1, 256>>>(edge_attr, arr, eidx,
                                             W1, W2, W3, Wf1,
                                             g1, be1, m1, v1,
                                             g2, be2, m2, v2,
                                             g3, be3, m3, v3);

    const int smem = STAGES * STAGE_BYTES;
    dim3 blk(128);
    dim3 grid5(5, E_ / 128);   // per-tile grid (co-scheduled columns -> L2 A-reuse)

    // Layer 1: A1 @ W1t -> relu -> BN affine -> h1   (sorted rows)
    gemm_f16<<<grid5, blk, smem>>>(a1, KP1, w1t, KP1, b1, s1p, t1p,
                                   h1, HP, EMB_, KP1 / 64, 0);
    // Layer 2: h1 @ W2t -> relu -> BN affine -> h2
    gemm_f16<<<grid5, blk, smem>>>(h1, HP, w2t, HP, b2, s2p, t2p,
                                   h2, HP, EMB_, HP / 64, 0);
    // Layer 3 + fused pool: h2 @ W3t -> relu -> (p @ Wf1t slice) -> g_gsum
    gemm_f16<<<grid5, blk, smem>>>(h2, HP, w3t, HP, b3, nullptr, nullptr,
                                   nullptr, 0, EMB_, HP / 64, 3);
    // Head
    head_kernel<<<G_, HID_>>>(bf1, Wf2, bf2, out);
}

// round 15
// speedup vs baseline: 1.0743x; 1.0743x over previous
#include <cuda_runtime.h>
#include <cuda_fp16.h>
#include <cstdint>

// Problem constants
#define E_    131072
#define G_    64
#define ED_   2049
#define KIN_  2055
#define EMB_  625
#define HID_  128
#define OUT_  2
#define EPSF  1e-5f

#define KP1   2112     // padded K for layer 1 (multiple of 64)
#define HP    640      // padded N / K pitch for h buffers & weights
#define STAGES 3
#define STAGE_BYTES 32768   // A 16KB + B 16KB (128 rows x 128B, k-tile = 64 halves)
#define NBLK  512           // E_/256 edge-processing blocks

// ---------------- device scratch (allocation-free) ----------------
__device__ __half g_A1[(size_t)E_ * KP1];    // sorted edge order
__device__ __half g_h1[(size_t)E_ * HP];
__device__ __half g_h2[(size_t)E_ * HP];
__device__ __half g_W1t[HP * KP1];
__device__ __half g_W2t[HP * HP];
__device__ __half g_W3t[HP * HP];
__device__ __half g_Wf1t[HID_ * HP];
__device__ float g_s1[EMB_], g_t1[EMB_];
__device__ float g_s2[EMB_], g_t2[EMB_];
__device__ float g_s3[EMB_], g_t3[EMB_];
__device__ float g_c0[HID_];
__device__ int   g_ebatch[E_];       // batch id per edge (original order)
__device__ int   g_perm[E_];         // sorted-pos -> original edge
__device__ int   g_ebatch_s[E_];     // batch id per sorted pos
__device__ int   g_bhist[NBLK * G_]; // per-block hist -> per-block base
__device__ float g_cnt[G_];
__device__ float g_gsum[G_ * HID_];

// ---------------- helpers ----------------
__device__ __forceinline__ uint32_t smem_u32(const void* p) {
    return (uint32_t)__cvta_generic_to_shared(p);
}
__device__ __forceinline__ void cp16(uint32_t dst, const void* src) {
    asm volatile("cp.async.cg.shared.global [%0], [%1], 16;\n" :: "r"(dst), "l"(src));
}
#define CP_COMMIT() asm volatile("cp.async.commit_group;\n" ::: "memory")
#define CP_WAIT1()  asm volatile("cp.async.wait_group 1;\n" ::: "memory")
#define CP_WAIT0()  asm volatile("cp.async.wait_group 0;\n" ::: "memory")

__device__ __forceinline__ void ldsm4(uint32_t& r0, uint32_t& r1, uint32_t& r2, uint32_t& r3,
                                      uint32_t addr) {
    asm volatile("ldmatrix.sync.aligned.m8n8.x4.shared.b16 {%0,%1,%2,%3}, [%4];"
                 : "=r"(r0), "=r"(r1), "=r"(r2), "=r"(r3) : "r"(addr));
}

#define MMA_F16(d, a, b0, b1)                                           \
    asm volatile(                                                       \
        "mma.sync.aligned.m16n8k16.row.col.f32.f16.f16.f32 "            \
        "{%0,%1,%2,%3}, {%4,%5,%6,%7}, {%8,%9}, {%0,%1,%2,%3};"         \
        : "+f"(d[0]), "+f"(d[1]), "+f"(d[2]), "+f"(d[3])                \
        : "r"(a[0]), "r"(a[1]), "r"(a[2]), "r"(a[3]), "r"(b0), "r"(b1))

// ---------------- prep kernels ----------------
__global__ void prep0_kernel(const float* __restrict__ g1, const float* __restrict__ be1,
                             const float* __restrict__ m1, const float* __restrict__ v1,
                             const float* __restrict__ g2, const float* __restrict__ be2,
                             const float* __restrict__ m2, const float* __restrict__ v2,
                             const float* __restrict__ g3, const float* __restrict__ be3,
                             const float* __restrict__ m3, const float* __restrict__ v3)
{
    int i = blockIdx.x * blockDim.x + threadIdx.x;
    if (i < EMB_) {
        float s1 = g1[i] / sqrtf(v1[i] + EPSF);
        g_s1[i] = s1; g_t1[i] = be1[i] - m1[i] * s1;
        float s2 = g2[i] / sqrtf(v2[i] + EPSF);
        g_s2[i] = s2; g_t2[i] = be2[i] - m2[i] * s2;
        float s3 = g3[i] / sqrtf(v3[i] + EPSF);
        g_s3[i] = s3; g_t3[i] = be3[i] - m3[i] * s3;
    }
    if (i < G_ * HID_) g_gsum[i] = 0.0f;
}

// per-block histogram of batch ids (no global atomics)
__global__ void prep_edge_kernel(const int* __restrict__ eidx,
                                 const int* __restrict__ batch)
{
    __shared__ int hist[G_];
    int t = threadIdx.x;
    if (t < G_) hist[t] = 0;
    __syncthreads();
    int e = blockIdx.x * blockDim.x + t;
    int b = batch[eidx[e]];
    g_ebatch[e] = b;
    atomicAdd(&hist[b], 1);
    __syncthreads();
    if (t < G_) g_bhist[blockIdx.x * G_ + t] = hist[t];
}

// column prefix: g_bhist[blk][b] -> global base for (blk, b); g_cnt[b] = total
__global__ void prep_prefix_kernel()   // 1 block, 64 threads
{
    __shared__ int tot[G_];
    int b = threadIdx.x;
    int t = 0;
    for (int blk = 0; blk < NBLK; blk++) t += g_bhist[blk * G_ + b];
    tot[b] = t;
    g_cnt[b] = (float)t;
    __syncthreads();
    int off = 0;
    for (int i = 0; i < b; i++) off += tot[i];
    int run = off;
    for (int blk = 0; blk < NBLK; blk++) {
        int h = g_bhist[blk * G_ + b];
        g_bhist[blk * G_ + b] = run;
        run += h;
    }
}

__global__ void scatter_kernel()
{
    __shared__ int cnt[G_];
    int t = threadIdx.x;
    if (t < G_) cnt[t] = 0;
    __syncthreads();
    int e = blockIdx.x * blockDim.x + t;
    int b = g_ebatch[e];
    int r = atomicAdd(&cnt[b], 1);
    int pos = g_bhist[blockIdx.x * G_ + b] + r;
    g_perm[pos] = e;
    g_ebatch_s[pos] = b;
}

// Build fp16 concatenated A1 in SORTED order: row p <- edge perm[p].
// 256 threads x 8 floats = 2048 main cols in ONE straight-line iteration:
// 8 independent LDG.32 per thread (MLP=8) -> one 16B store (16-aligned).
__global__ void build_a1_kernel(const float* __restrict__ ea,
                                const float* __restrict__ arr,
                                const int* __restrict__ eidx)
{
    const int p = blockIdx.x;
    const int e = g_perm[p];
    const float* src = ea + (size_t)e * ED_;
    __half* dst = g_A1 + (size_t)p * KP1;
    const int t = threadIdx.x;

    {
        const int k = t * 8;
        float f0 = src[k + 0], f1 = src[k + 1], f2 = src[k + 2], f3 = src[k + 3];
        float f4 = src[k + 4], f5 = src[k + 5], f6 = src[k + 6], f7 = src[k + 7];
        __half2 p0 = __floats2half2_rn(f0, f1);
        __half2 p1 = __floats2half2_rn(f2, f3);
        __half2 p2 = __floats2half2_rn(f4, f5);
        __half2 p3 = __floats2half2_rn(f6, f7);
        uint4 u;
        u.x = *(uint32_t*)&p0;
        u.y = *(uint32_t*)&p1;
        u.z = *(uint32_t*)&p2;
        u.w = *(uint32_t*)&p3;
        *(uint4*)(dst + k) = u;     // dst row pitch 4224B, offset 16t -> 16B aligned
    }
    if (t < 64) {
        int k = 2048 + t;
        float v;
        if (k < ED_) {
            v = src[k];
        } else if (k < ED_ + 3) {
            v = arr[3 * eidx[e] + (k - ED_)];
        } else if (k < ED_ + 6) {
            v = arr[3 * eidx[E_ + e] + (k - ED_ - 3)];
        } else {
            v = 0.0f;
        }
        dst[k] = __float2half_rn(v);
    }
}

// All four transposed weights in one launch (flat index, k-fast per segment)
#define WSEG1 ((size_t)HP * KP1)
#define WSEG2 (WSEG1 + (size_t)HP * HP)
#define WSEG3 (WSEG2 + (size_t)HP * HP)
#define WSEG4 (WSEG3 + (size_t)HID_ * HP)
__global__ void prep_wt_all(const float* __restrict__ W1, const float* __restrict__ W2,
                            const float* __restrict__ W3, const float* __restrict__ Wf1)
{
    size_t idx = (size_t)blockIdx.x * blockDim.x + threadIdx.x;
    if (idx < WSEG1) {
        int n = (int)(idx / KP1), k = (int)(idx % KP1);
        float v = (k < KIN_ && n < EMB_) ? W1[(size_t)k * EMB_ + n] : 0.0f;
        g_W1t[idx] = __float2half_rn(v);
    } else if (idx < WSEG2) {
        size_t j = idx - WSEG1;
        int n = (int)(j / HP), k = (int)(j % HP);
        float v = (k < EMB_ && n < EMB_) ? W2[(size_t)k * EMB_ + n] : 0.0f;
        g_W2t[j] = __float2half_rn(v);
    } else if (idx < WSEG3) {
        size_t j = idx - WSEG2;
        int n = (int)(j / HP), k = (int)(j % HP);
        float v = (k < EMB_ && n < EMB_) ? W3[(size_t)k * EMB_ + n] : 0.0f;
        g_W3t[j] = __float2half_rn(v);
    } else if (idx < WSEG4) {
        size_t j = idx - WSEG3;
        int n = (int)(j / HP), k = (int)(j % HP);
        float v = (k < EMB_ && n < HID_) ? Wf1[(size_t)k * HID_ + n] * g_s3[k] : 0.0f;
        g_Wf1t[j] = __float2half_rn(v);
    }
}

// c0[n] = t3 @ Wf1[:, n]
__global__ void prep_c0_kernel(const float* __restrict__ Wf1)
{
    int n = threadIdx.x;
    float c0 = 0.0f;
    for (int k = 0; k < EMB_; k++) c0 = fmaf(g_t3[k], Wf1[k * HID_ + n], c0);
    g_c0[n] = c0;
}

// ---------------- fp16 tensor-core GEMM: cp.async pipeline + ldmatrix ----------------
//   emode 0: h = max(z + bias, 0) * scale + shift  -> fp16 store (0 for n >= Nreal)
//   emode 3: p = max(z + bias, 0) -> smem; fused pool: p @ Wf1t[k=col0..col0+128)
//            -> segment-sum into g_gsum (rows are batch-sorted). No global store.
__global__ __launch_bounds__(128)
void gemm_f16(const __half* __restrict__ A, int lda,
              const __half* __restrict__ Bt, int ldbt,
              const float* __restrict__ bias,
              const float* __restrict__ scale,
              const float* __restrict__ shift,
              __half* __restrict__ C, int ldc,
              int Nreal, int ktiles, int emode)
{
    extern __shared__ __align__(16) char smem_raw[];
    const uint32_t sb = smem_u32(smem_raw);

    const int tid  = threadIdx.x;
    const int lane = tid & 31;
    const int w    = tid >> 5;            // 0..3
    const int wm   = (w & 1) * 64;
    const int wn   = (w >> 1) * 64;
    const int row0 = blockIdx.y * 128;
    const int col0 = blockIdx.x * 128;

    const __half* Abase = A  + (size_t)row0 * lda;
    const __half* Bbase = Bt + (size_t)col0 * ldbt;

    // ldmatrix lane address components
    const int rA  = wm + (lane & 15);
    const int hiA = lane >> 4;
    const int xa  = rA & 7;
    const int rB  = wn + ((lane >> 4) & 1) * 8 + (lane & 7);
    const int hiB = (lane >> 3) & 1;
    const int xb  = rB & 7;

    float acc[4][8][4];
#pragma unroll
    for (int mi = 0; mi < 4; mi++)
#pragma unroll
        for (int ni = 0; ni < 8; ni++)
#pragma unroll
            for (int c = 0; c < 4; c++) acc[mi][ni][c] = 0.0f;

    auto stage = [&](int s, int kt) {
        uint32_t sA = sb + s * STAGE_BYTES;
        uint32_t sB = sA + 16384;
        const __half* Ak = Abase + kt * 64;
        const __half* Bk = Bbase + kt * 64;
#pragma unroll
        for (int i = 0; i < 8; i++) {
            int id = i * 128 + tid;
            int m  = id >> 3;
            int c  = id & 7;
            cp16(sA + m * 128 + ((c ^ (m & 7)) << 4), Ak + (size_t)m * lda + c * 8);
        }
#pragma unroll
        for (int i = 0; i < 8; i++) {
            int id = i * 128 + tid;
            int n  = id >> 3;
            int c  = id & 7;
            cp16(sB + n * 128 + ((c ^ (n & 7)) << 4), Bk + (size_t)n * ldbt + c * 8);
        }
    };

    // the shared inner-loop body over one staged ktile
    auto compute_tile = [&](uint32_t sA, uint32_t sB) {
#pragma unroll
        for (int k16 = 0; k16 < 4; k16++) {
            uint32_t a[4][4];
#pragma unroll
            for (int mi = 0; mi < 4; mi++) {
                uint32_t addr = sA + (rA + mi * 16) * 128
                              + ((uint32_t)((k16 * 2 + hiA) ^ xa) << 4);
                ldsm4(a[mi][0], a[mi][1], a[mi][2], a[mi][3], addr);
            }
            uint32_t bf[4][4];
#pragma unroll
            for (int nj = 0; nj < 4; nj++) {
                uint32_t addr = sB + (rB + nj * 16) * 128
                              + ((uint32_t)((k16 * 2 + hiB) ^ xb) << 4);
                ldsm4(bf[nj][0], bf[nj][1], bf[nj][2], bf[nj][3], addr);
            }
#pragma unroll
            for (int mi = 0; mi < 4; mi++) {
#pragma unroll
                for (int nj = 0; nj < 4; nj++) {
                    MMA_F16(acc[mi][2 * nj],     a[mi], bf[nj][0], bf[nj][1]);
                    MMA_F16(acc[mi][2 * nj + 1], a[mi], bf[nj][2], bf[nj][3]);
                }
            }
        }
    };

    // prologue: stages 0 and 1
    stage(0, 0);
    CP_COMMIT();
    stage(1, 1);
    CP_COMMIT();

    for (int kt = 0; kt < ktiles; kt++) {
        CP_WAIT1();          // stage kt arrived (allow kt+1 pending)
        __syncthreads();     // all threads past compute(kt-1) -> safe to overwrite

        int pf = kt + 2;
        if (pf < ktiles) stage(pf % STAGES, pf);
        CP_COMMIT();

        const int s = kt % STAGES;
        compute_tile(sb + s * STAGE_BYTES, sb + s * STAGE_BYTES + 16384);
    }

    // ---- epilogue ----
    const int g  = lane >> 2;
    const int tg = lane & 3;

    if (emode == 0) {
#pragma unroll
        for (int mi = 0; mi < 4; mi++) {
            int r_lo = row0 + wm + mi * 16 + g;
            __half* crow_lo = C + (size_t)r_lo * ldc;
            __half* crow_hi = crow_lo + (size_t)8 * ldc;
#pragma unroll
            for (int ni = 0; ni < 8; ni++) {
                int cc = col0 + wn + ni * 8 + tg * 2;
                float z0 = 0.0f, z1 = 0.0f, z2 = 0.0f, z3 = 0.0f;
                if (cc < Nreal) {
                    float b0 = bias[cc];
                    float sc0 = scale[cc], sh0 = shift[cc];
                    z0 = fmaxf(acc[mi][ni][0] + b0, 0.0f) * sc0 + sh0;
                    z2 = fmaxf(acc[mi][ni][2] + b0, 0.0f) * sc0 + sh0;
                }
                if (cc + 1 < Nreal) {
                    float b1 = bias[cc + 1];
                    float sc1 = scale[cc + 1], sh1 = shift[cc + 1];
                    z1 = fmaxf(acc[mi][ni][1] + b1, 0.0f) * sc1 + sh1;
                    z3 = fmaxf(acc[mi][ni][3] + b1, 0.0f) * sc1 + sh1;
                }
                *(__half2*)&crow_lo[cc] = __floats2half2_rn(z0, z1);
                *(__half2*)&crow_hi[cc] = __floats2half2_rn(z2, z3);
            }
        }
        return;
    }

    // ======== emode 3: layer 3 with fused pool ========
    __syncthreads();   // all warps done with stage smem

    // stage Wf1t slices (k = col0 + it*64, n = 0..127) into B-areas of stages 0,1
#pragma unroll
    for (int it = 0; it < 2; it++) {
        uint32_t sB = sb + it * STAGE_BYTES + 16384;
        const __half* Bk = g_Wf1t + col0 + it * 64;
#pragma unroll
        for (int i = 0; i < 8; i++) {
            int id = i * 128 + tid;
            int n  = id >> 3;
            int c  = id & 7;
            cp16(sB + n * 128 + ((c ^ (n & 7)) << 4), Bk + (size_t)n * HP + c * 8);
        }
    }
    CP_COMMIT();

    // store p = fp16(relu(z + b3)) into A-areas of stages 0,1 (same swizzle)
#pragma unroll
    for (int mi = 0; mi < 4; mi++) {
        int m_lo = wm + mi * 16 + g;     // block-local rows
        int m_hi = m_lo + 8;
#pragma unroll
        for (int ni = 0; ni < 8; ni++) {
            int cc = wn + ni * 8 + tg * 2;          // block-local col 0..127
            int gcc = col0 + cc;
            float z0 = 0.0f, z1 = 0.0f, z2 = 0.0f, z3 = 0.0f;
            if (gcc < Nreal) {
                float b0 = bias[gcc];
                z0 = fmaxf(acc[mi][ni][0] + b0, 0.0f);
                z2 = fmaxf(acc[mi][ni][2] + b0, 0.0f);
            }
            if (gcc + 1 < Nreal) {
                float b1 = bias[gcc + 1];
                z1 = fmaxf(acc[mi][ni][1] + b1, 0.0f);
                z3 = fmaxf(acc[mi][ni][3] + b1, 0.0f);
            }
            int it = cc >> 6;                       // which stage A-area
            int jp = (cc & 63) >> 1;                // half2 pair index 0..31
            int chunk = jp >> 2;                    // 16B chunk 0..7
            int within = (jp & 3) * 4;
            __half2 h_lo = __floats2half2_rn(z0, z1);
            __half2 h_hi = __floats2half2_rn(z2, z3);
            char* a_area = smem_raw + it * STAGE_BYTES;
            *(uint32_t*)(a_area + m_lo * 128 + ((chunk ^ (m_lo & 7)) << 4) + within)
                = *(uint32_t*)&h_lo;
            *(uint32_t*)(a_area + m_hi * 128 + ((chunk ^ (m_hi & 7)) << 4) + within)
                = *(uint32_t*)&h_hi;
        }
    }

    CP_WAIT0();
    __syncthreads();

    // pool GEMM: 2 ktile iterations, acc reused as 128x128 pool accumulator
#pragma unroll
    for (int mi = 0; mi < 4; mi++)
#pragma unroll
        for (int ni = 0; ni < 8; ni++)
#pragma unroll
            for (int c = 0; c < 4; c++) acc[mi][ni][c] = 0.0f;

    compute_tile(sb, sb + 16384);
    compute_tile(sb + STAGE_BYTES, sb + STAGE_BYTES + 16384);

    // segment-sum epilogue (rows batch-sorted)
    {
        const int b0 = g_ebatch_s[row0];
        const int bL = g_ebatch_s[row0 + 127];
        if (b0 == bL) {
            float s[8][2];
#pragma unroll
            for (int ni = 0; ni < 8; ni++) {
                s[ni][0] = 0.0f; s[ni][1] = 0.0f;
#pragma unroll
                for (int mi = 0; mi < 4; mi++) {
                    s[ni][0] += acc[mi][ni][0] + acc[mi][ni][2];
                    s[ni][1] += acc[mi][ni][1] + acc[mi][ni][3];
                }
            }
#pragma unroll
            for (int off = 4; off <= 16; off <<= 1) {
#pragma unroll
                for (int ni = 0; ni < 8; ni++) {
                    s[ni][0] += __shfl_xor_sync(0xffffffffu, s[ni][0], off);
                    s[ni][1] += __shfl_xor_sync(0xffffffffu, s[ni][1], off);
                }
            }
            __shared__ float red[2][128];
            if (lane < 4) {
#pragma unroll
                for (int ni = 0; ni < 8; ni++) {
                    red[wm >> 6][wn + ni * 8 + lane * 2 + 0] = s[ni][0];
                    red[wm >> 6][wn + ni * 8 + lane * 2 + 1] = s[ni][1];
                }
            }
            __syncthreads();
            atomicAdd(&g_gsum[b0 * HID_ + tid], red[0][tid] + red[1][tid]);
        } else {
#pragma unroll
            for (int mi = 0; mi < 4; mi++) {
                int r_lo = row0 + wm + mi * 16 + g;
                int b_lo = g_ebatch_s[r_lo];
                int b_hi = g_ebatch_s[r_lo + 8];
#pragma unroll
                for (int ni = 0; ni < 8; ni++) {
                    int cc = wn + ni * 8 + tg * 2;
                    atomicAdd(&g_gsum[b_lo * HID_ + cc],     acc[mi][ni][0]);
                    atomicAdd(&g_gsum[b_lo * HID_ + cc + 1], acc[mi][ni][1]);
                    atomicAdd(&g_gsum[b_hi * HID_ + cc],     acc[mi][ni][2]);
                    atomicAdd(&g_gsum[b_hi * HID_ + cc + 1], acc[mi][ni][3]);
                }
            }
        }
    }
}

// ---------------- head: mean + 2-layer MLP ----------------
__global__ void head_kernel(const float* __restrict__ bf1,
                            const float* __restrict__ Wf2,
                            const float* __restrict__ bf2,
                            float* __restrict__ out)
{
    const int g = blockIdx.x;
    const int n = threadIdx.x;
    float cnt = g_cnt[g];
    float v = (cnt > 0.0f) ? (g_gsum[g * HID_ + n] / cnt + g_c0[n]) : 0.0f;
    float h = fmaxf(v + bf1[n], 0.0f);

    __shared__ float s0[HID_], s1[HID_];
    s0[n] = h * Wf2[n * OUT_ + 0];
    s1[n] = h * Wf2[n * OUT_ + 1];
    __syncthreads();
    for (int off = HID_ / 2; off > 0; off >>= 1) {
        if (n < off) { s0[n] += s0[n + off]; s1[n] += s1[n + off]; }
        __syncthreads();
    }
    if (n == 0) {
        out[g * OUT_ + 0] = s0[0] + bf2[0];
        out[g * OUT_ + 1] = s1[0] + bf2[1];
    }
}

// ---------------- launch ----------------
extern "C" void kernel_launch(void* const* d_in, const int* in_sizes, int n_in,
                              void* d_out, int out_size)
{
    (void)in_sizes; (void)n_in; (void)out_size;

    const float* edge_attr = (const float*)d_in[0];
    const float* arr       = (const float*)d_in[1];
    const int*   eidx      = (const int*)d_in[2];
    const int*   batch     = (const int*)d_in[3];
    const float *W1 = (const float*)d_in[4],  *b1 = (const float*)d_in[5];
    const float *g1 = (const float*)d_in[6],  *be1 = (const float*)d_in[7];
    const float *m1 = (const float*)d_in[8],  *v1 = (const float*)d_in[9];
    const float *W2 = (const float*)d_in[10], *b2 = (const float*)d_in[11];
    const float *g2 = (const float*)d_in[12], *be2 = (const float*)d_in[13];
    const float *m2 = (const float*)d_in[14], *v2 = (const float*)d_in[15];
    const float *W3 = (const float*)d_in[16], *b3 = (const float*)d_in[17];
    const float *g3 = (const float*)d_in[18], *be3 = (const float*)d_in[19];
    const float *m3 = (const float*)d_in[20], *v3 = (const float*)d_in[21];
    const float *Wf1 = (const float*)d_in[22], *bf1 = (const float*)d_in[23];
    const float *Wf2 = (const float*)d_in[24], *bf2 = (const float*)d_in[25];
    float* out = (float*)d_out;

    __half *a1, *h1, *h2, *w1t, *w2t, *w3t;
    float *s1p, *t1p, *s2p, *t2p;
    cudaGetSymbolAddress((void**)&a1,   g_A1);
    cudaGetSymbolAddress((void**)&h1,   g_h1);
    cudaGetSymbolAddress((void**)&h2,   g_h2);
    cudaGetSymbolAddress((void**)&w1t,  g_W1t);
    cudaGetSymbolAddress((void**)&w2t,  g_W2t);
    cudaGetSymbolAddress((void**)&w3t,  g_W3t);
    cudaGetSymbolAddress((void**)&s1p,  g_s1);
    cudaGetSymbolAddress((void**)&t1p,  g_t1);
    cudaGetSymbolAddress((void**)&s2p,  g_s2);
    cudaGetSymbolAddress((void**)&t2p,  g_t2);

    cudaFuncSetAttribute(gemm_f16, cudaFuncAttributeMaxDynamicSharedMemorySize,
                         STAGES * STAGE_BYTES);

    // prep
    prep0_kernel<<<32, 256>>>(g1, be1, m1, v1, g2, be2, m2, v2, g3, be3, m3, v3);
    prep_edge_kernel<<<NBLK, 256>>>(eidx, batch);
    prep_prefix_kernel<<<1, G_>>>();
    scatter_kernel<<<NBLK, 256>>>();
    build_a1_kernel<<<E_, 256>>>(edge_attr, arr, eidx);
    prep_wt_all<<<(int)((WSEG4 + 255) / 256), 256>>>(W1, W2, W3, Wf1);
    prep_c0_kernel<<<1, HID_>>>(Wf1);

    const int smem = STAGES * STAGE_BYTES;
    dim3 blk(128);
    dim3 grid5(5, E_ / 128);   // per-tile grid (co-scheduled columns -> L2 A-reuse)

    // Layer 1: A1 @ W1t -> relu -> BN affine -> h1   (sorted rows)
    gemm_f16<<<grid5, blk, smem>>>(a1, KP1, w1t, KP1, b1, s1p, t1p,
                                   h1, HP, EMB_, KP1 / 64, 0);
    // Layer 2: h1 @ W2t -> relu -> BN affine -> h2
    gemm_f16<<<grid5, blk, smem>>>(h1, HP, w2t, HP, b2, s2p, t2p,
                                   h2, HP, EMB_, HP / 64, 0);
    // Layer 3 + fused pool: h2 @ W3t -> relu -> (p @ Wf1t slice) -> g_gsum
    gemm_f16<<<grid5, blk, smem>>>(h2, HP, w3t, HP, b3, nullptr, nullptr,
                                   nullptr, 0, EMB_, HP / 64, 3);
    // Head
    head_kernel<<<G_, HID_>>>(bf1, Wf2, bf2, out);
}